// round 2
// baseline (speedup 1.0000x reference)
#include <cuda_runtime.h>
#include <math.h>

#define BB 256     // batch
#define TT 512     // time steps
#define DIN 128    // input dim
#define HH 256     // hidden
#define G4 1024    // 4*H
#define OUTF 128   // final out features
#define NB_CTAS 128
#define BHH (BB * HH)

// ---------------- scratch (device globals; no allocations allowed) ----------
__device__ float g_XP[(size_t)TT * BB * G4];    // x_proj, layout [T, B, 4H]
__device__ float g_HSEQ[(size_t)TT * BB * HH];  // layer-0 h sequence [T,B,H]
__device__ float g_h[2][BHH];                   // ping-pong hidden state
__device__ unsigned g_count;                    // grid barrier arrival counter

// ---------------- init: zero h[0] and barrier counter ------------------------
__global__ void init_kernel() {
    int i = blockIdx.x * blockDim.x + threadIdx.x;
    if (i < BHH) g_h[0][i] = 0.f;
    if (i == 0) g_count = 0u;
}

// ---------------- generic GEMM + bias (validated in R1) ----------------------
// out[(t*B + row)*ldOut + col] = sum_k A[row,t,k] * W[col,k] (+ b1[col]+b2[col])
template <int K>
__global__ void gemm_bias_kernel(const float* __restrict__ A,
                                 size_t rowStrideB, size_t strideT,
                                 const float* __restrict__ W,
                                 const float* __restrict__ b1,
                                 const float* __restrict__ b2,
                                 float* __restrict__ outp, int ldOut)
{
    __shared__ __align__(16) float As[64][68];
    __shared__ __align__(16) float Ws[64][68];

    const int t   = blockIdx.z;
    const int bb  = blockIdx.y * 64;
    const int nn  = blockIdx.x * 64;
    const int tid = threadIdx.x;
    const int r0  = tid & 15;
    const int c0  = tid >> 4;

    float acc[4][4];
#pragma unroll
    for (int m = 0; m < 4; m++)
#pragma unroll
        for (int n = 0; n < 4; n++) acc[m][n] = 0.f;

    const float* Abase = A + (size_t)bb * rowStrideB + (size_t)t * strideT;
    const float* Wbase = W + (size_t)nn * K;

    for (int kt = 0; kt < K; kt += 64) {
#pragma unroll
        for (int i = 0; i < 4; i++) {
            int lin = i * 256 + tid;
            int row = lin >> 4;
            int c4  = (lin & 15) * 4;
            *(float4*)&As[row][c4] =
                *(const float4*)(Abase + (size_t)row * rowStrideB + kt + c4);
            *(float4*)&Ws[row][c4] =
                *(const float4*)(Wbase + (size_t)row * K + kt + c4);
        }
        __syncthreads();

#pragma unroll
        for (int k = 0; k < 64; k += 4) {
            float4 a4[4], w4[4];
#pragma unroll
            for (int m = 0; m < 4; m++) a4[m] = *(float4*)&As[r0 + 16 * m][k];
#pragma unroll
            for (int n = 0; n < 4; n++) w4[n] = *(float4*)&Ws[c0 + 16 * n][k];
#pragma unroll
            for (int m = 0; m < 4; m++)
#pragma unroll
                for (int n = 0; n < 4; n++) {
                    acc[m][n] += a4[m].x * w4[n].x;
                    acc[m][n] += a4[m].y * w4[n].y;
                    acc[m][n] += a4[m].z * w4[n].z;
                    acc[m][n] += a4[m].w * w4[n].w;
                }
        }
        __syncthreads();
    }

#pragma unroll
    for (int m = 0; m < 4; m++)
#pragma unroll
        for (int n = 0; n < 4; n++) {
            int row = bb + r0 + 16 * m;
            int col = nn + c0 + 16 * n;
            float bias = (b1 != nullptr) ? (b1[col] + b2[col]) : 0.f;
            outp[((size_t)t * BB + row) * ldOut + col] = acc[m][n] + bias;
        }
}

// ---------------- persistent LSTM layer kernel --------------------------------
// Grid: 128 CTAs x 128 threads. CTA (jt,bt) owns hidden slice jj..jj+15 and
// batch slice bb..bb+31 for the ENTIRE sequence. W_hh slice in SMEM once,
// c state in registers, h exchanged via global ping-pong + grid barrier.
// SMEM: Ws 64x260 floats (64 gate-rows x K=256) + Hs 32x260 floats.
#define WPAD 260
#define SMEM_FLOATS (64 * WPAD + 32 * WPAD)

__device__ __forceinline__ void grid_bar(unsigned target) {
    __syncthreads();
    if (threadIdx.x == 0) {
        __threadfence();
        atomicAdd(&g_count, 1u);
        while (*((volatile unsigned*)&g_count) < target) {}
        __threadfence();
    }
    __syncthreads();
}

__global__ void lstm_persist_kernel(const float* __restrict__ xp,   // [T,B,4H]
                                    const float* __restrict__ Whh,  // [4H,H]
                                    float* __restrict__ hbuf,       // [2][B,H]
                                    float* __restrict__ hseq)       // [T,B,H] or null
{
    extern __shared__ float sm[];
    float* Ws = sm;               // [64][WPAD]
    float* Hs = sm + 64 * WPAD;   // [32][WPAD]

    const int tid = threadIdx.x;
    const int jt  = blockIdx.x & 15;
    const int bt  = blockIdx.x >> 4;
    const int jj  = jt * 16;
    const int bb  = bt * 32;
    const int jl  = tid >> 3;    // 0..15 hidden unit within tile
    const int br  = tid & 7;     // batch sub-row; rows br, br+8, br+16, br+24
    const int j   = jj + jl;

    // ---- load W_hh slice once: smem row = g*16 + jloc, global row = g*256+jj+jloc
#pragma unroll
    for (int i = 0; i < 32; i++) {
        int lin  = i * 128 + tid;        // 0..4095 float4 units
        int srow = lin >> 6;             // 0..63
        int c4   = (lin & 63) * 4;
        int g    = srow >> 4;
        int jloc = srow & 15;
        *(float4*)&Ws[srow * WPAD + c4] =
            *(const float4*)(Whh + (size_t)(g * HH + jj + jloc) * HH + c4);
    }

    float cacc[4] = {0.f, 0.f, 0.f, 0.f};
    __syncthreads();

    for (int t = 0; t < TT; t++) {
        // ---- load h tile (32 x 256) from ping buffer, L2-coherent
        const float* hin = hbuf + (size_t)(t & 1) * BHH;
#pragma unroll
        for (int i = 0; i < 16; i++) {
            int lin = i * 128 + tid;     // 0..2047 float4 units
            int row = lin >> 6;          // 0..31
            int c4  = (lin & 63) * 4;
            float4 v = __ldcg((const float4*)(hin + (size_t)(bb + row) * HH + c4));
            *(float4*)&Hs[row * WPAD + c4] = v;
        }
        __syncthreads();

        // ---- prefetch x_proj values for this step (consumed in epilogue)
        float xv[4][4];
        {
            const float* xpt = xp + (size_t)t * BB * G4;
#pragma unroll
            for (int m = 0; m < 4; m++) {
                const float* xr = xpt + (size_t)(bb + br + 8 * m) * G4;
#pragma unroll
                for (int g = 0; g < 4; g++)
                    xv[m][g] = __ldg(xr + g * HH + j);
            }
        }

        // ---- GEMM: acc[m][g] = h[b_m,:] . Whh[g*256+j,:]
        float acc[4][4];
#pragma unroll
        for (int m = 0; m < 4; m++)
#pragma unroll
            for (int g = 0; g < 4; g++) acc[m][g] = 0.f;

#pragma unroll 4
        for (int k = 0; k < HH; k += 4) {
            float4 h4[4], w4[4];
#pragma unroll
            for (int m = 0; m < 4; m++) h4[m] = *(float4*)&Hs[(br + 8 * m) * WPAD + k];
#pragma unroll
            for (int g = 0; g < 4; g++) w4[g] = *(float4*)&Ws[(g * 16 + jl) * WPAD + k];
#pragma unroll
            for (int m = 0; m < 4; m++)
#pragma unroll
                for (int g = 0; g < 4; g++) {
                    acc[m][g] += h4[m].x * w4[g].x;
                    acc[m][g] += h4[m].y * w4[g].y;
                    acc[m][g] += h4[m].z * w4[g].z;
                    acc[m][g] += h4[m].w * w4[g].w;
                }
        }

        // ---- gates + state update; write h to other ping buffer
        float* hout = hbuf + (size_t)((t + 1) & 1) * BHH;
#pragma unroll
        for (int m = 0; m < 4; m++) {
            int b = bb + br + 8 * m;
            float vi = acc[m][0] + xv[m][0];
            float vf = acc[m][1] + xv[m][1];
            float vg = acc[m][2] + xv[m][2];
            float vo = acc[m][3] + xv[m][3];

            float ig = 1.f / (1.f + expf(-vi));
            float fg = 1.f / (1.f + expf(-vf));
            float gg = tanhf(vg);
            float og = 1.f / (1.f + expf(-vo));

            float cn = fg * cacc[m] + ig * gg;
            cacc[m] = cn;
            float hn = og * tanhf(cn);
            __stcg(hout + (size_t)b * HH + j, hn);
            if (hseq != nullptr) hseq[(size_t)t * BHH + (size_t)b * HH + j] = hn;
        }

        grid_bar((unsigned)(t + 1) * NB_CTAS);
    }
}

// ---------------- launcher ---------------------------------------------------
extern "C" void kernel_launch(void* const* d_in, const int* in_sizes, int n_in,
                              void* d_out, int out_size)
{
    const float* x     = (const float*)d_in[0];
    const float* W_ih0 = (const float*)d_in[1];
    const float* W_hh0 = (const float*)d_in[2];
    const float* b_ih0 = (const float*)d_in[3];
    const float* b_hh0 = (const float*)d_in[4];
    const float* W_ih1 = (const float*)d_in[5];
    const float* W_hh1 = (const float*)d_in[6];
    const float* b_ih1 = (const float*)d_in[7];
    const float* b_hh1 = (const float*)d_in[8];
    const float* W_fc  = (const float*)d_in[9];
    float* outp = (float*)d_out;
    (void)in_sizes; (void)n_in; (void)out_size;

    float *XP, *HSEQ, *Hbuf;
    cudaGetSymbolAddress((void**)&XP,   g_XP);
    cudaGetSymbolAddress((void**)&HSEQ, g_HSEQ);
    cudaGetSymbolAddress((void**)&Hbuf, g_h);

    static bool attr_set = false;
    if (!attr_set) {
        cudaFuncSetAttribute(lstm_persist_kernel,
                             cudaFuncAttributeMaxDynamicSharedMemorySize,
                             SMEM_FLOATS * (int)sizeof(float));
        attr_set = true;
    }

    const dim3 gemmBlk(256);
    const size_t smemB = SMEM_FLOATS * sizeof(float);

    // ---------- layer 0 ----------
    init_kernel<<<(BHH + 255) / 256, 256>>>();
    gemm_bias_kernel<DIN><<<dim3(16, 4, TT), gemmBlk>>>(
        x, (size_t)TT * DIN, (size_t)DIN, W_ih0, b_ih0, b_hh0, XP, G4);
    lstm_persist_kernel<<<NB_CTAS, 128, smemB>>>(XP, W_hh0, Hbuf, HSEQ);

    // ---------- layer 1 ----------
    init_kernel<<<(BHH + 255) / 256, 256>>>();
    gemm_bias_kernel<HH><<<dim3(16, 4, TT), gemmBlk>>>(
        HSEQ, (size_t)HH, (size_t)BB * HH, W_ih1, b_ih1, b_hh1, XP, G4);
    lstm_persist_kernel<<<NB_CTAS, 128, smemB>>>(XP, W_hh1, Hbuf, nullptr);

    // ---------- final FC: out = h_last @ W_fc^T (layer-1 last h is in buf 0) --
    gemm_bias_kernel<HH><<<dim3(2, 4, 1), gemmBlk>>>(
        Hbuf, (size_t)HH, 0, W_fc, nullptr, nullptr, outp, OUTF);
}

// round 3
// speedup vs baseline: 1.0146x; 1.0146x over previous
#include <cuda_runtime.h>
#include <math.h>

#define BB 256     // batch
#define TT 512     // time steps
#define DIN 128    // input dim
#define HH 256     // hidden
#define G4 1024    // 4*H
#define OUTF 128   // final out features
#define NB_CTAS 128
#define BHH (BB * HH)
#define NGROUPS 8        // batch-tile groups of 16 CTAs
#define GROUP_CTAS 16

typedef unsigned long long ull;

// ---------------- scratch (device globals; no allocations allowed) ----------
__device__ float g_XP[(size_t)TT * BB * G4];    // x_proj, layout [T, B, 4H]
__device__ float g_HSEQ[(size_t)TT * BB * HH];  // layer-0 h sequence [T,B,H]
__device__ float g_h[2][BHH];                   // ping-pong hidden state
__device__ unsigned g_count[NGROUPS];           // per-group barrier counters

// ---------------- packed fp32x2 FMA (Blackwell 2x fp32 path) ----------------
__device__ __forceinline__ void ffma2(ull& d, ull a, ull b) {
    asm("fma.rn.f32x2 %0, %1, %2, %0;" : "+l"(d) : "l"(a), "l"(b));
}
__device__ __forceinline__ float red2(ull v) {
    float lo = __uint_as_float((unsigned)(v & 0xffffffffu));
    float hi = __uint_as_float((unsigned)(v >> 32));
    return lo + hi;
}
// fast stable sigmoid/tanh (MUFU EX2/RCP based; ~1e-7 rel op error)
__device__ __forceinline__ float fsig(float x) {
    return __fdividef(1.f, 1.f + __expf(-x));
}
__device__ __forceinline__ float ftanh(float x) {
    return 2.f * __fdividef(1.f, 1.f + __expf(-2.f * x)) - 1.f;
}

// ---------------- init: zero h[0] and barrier counters ------------------------
__global__ void init_kernel() {
    int i = blockIdx.x * blockDim.x + threadIdx.x;
    if (i < BHH) g_h[0][i] = 0.f;
    if (i < NGROUPS) g_count[i] = 0u;
}

// ---------------- generic GEMM + bias (f32x2 inner product) -------------------
// out[(t*B + row)*ldOut + col] = sum_k A[row,t,k] * W[col,k] (+ b1[col]+b2[col])
template <int K>
__global__ void gemm_bias_kernel(const float* __restrict__ A,
                                 size_t rowStrideB, size_t strideT,
                                 const float* __restrict__ W,
                                 const float* __restrict__ b1,
                                 const float* __restrict__ b2,
                                 float* __restrict__ outp, int ldOut)
{
    __shared__ __align__(16) float As[64][68];
    __shared__ __align__(16) float Ws[64][68];

    const int t   = blockIdx.z;
    const int bb  = blockIdx.y * 64;
    const int nn  = blockIdx.x * 64;
    const int tid = threadIdx.x;
    const int r0  = tid & 15;
    const int c0  = tid >> 4;

    ull acc2[4][4];
#pragma unroll
    for (int m = 0; m < 4; m++)
#pragma unroll
        for (int n = 0; n < 4; n++) acc2[m][n] = 0ull;

    const float* Abase = A + (size_t)bb * rowStrideB + (size_t)t * strideT;
    const float* Wbase = W + (size_t)nn * K;

    for (int kt = 0; kt < K; kt += 64) {
#pragma unroll
        for (int i = 0; i < 4; i++) {
            int lin = i * 256 + tid;
            int row = lin >> 4;
            int c4  = (lin & 15) * 4;
            *(float4*)&As[row][c4] =
                *(const float4*)(Abase + (size_t)row * rowStrideB + kt + c4);
            *(float4*)&Ws[row][c4] =
                *(const float4*)(Wbase + (size_t)row * K + kt + c4);
        }
        __syncthreads();

#pragma unroll
        for (int k = 0; k < 64; k += 4) {
            ulonglong2 a2[4], w2[4];
#pragma unroll
            for (int m = 0; m < 4; m++) a2[m] = *(ulonglong2*)&As[r0 + 16 * m][k];
#pragma unroll
            for (int n = 0; n < 4; n++) w2[n] = *(ulonglong2*)&Ws[c0 + 16 * n][k];
#pragma unroll
            for (int m = 0; m < 4; m++)
#pragma unroll
                for (int n = 0; n < 4; n++) {
                    ffma2(acc2[m][n], a2[m].x, w2[n].x);
                    ffma2(acc2[m][n], a2[m].y, w2[n].y);
                }
        }
        __syncthreads();
    }

#pragma unroll
    for (int m = 0; m < 4; m++)
#pragma unroll
        for (int n = 0; n < 4; n++) {
            int row = bb + r0 + 16 * m;
            int col = nn + c0 + 16 * n;
            float bias = (b1 != nullptr) ? (b1[col] + b2[col]) : 0.f;
            outp[((size_t)t * BB + row) * ldOut + col] = red2(acc2[m][n]) + bias;
        }
}

// ---------------- persistent LSTM layer kernel --------------------------------
// 128 CTAs x 128 threads. CTA (jt,bt): hidden slice jj..jj+15, batch bb..bb+31.
// W_hh slice resident in SMEM, c in registers, h via global ping-pong.
// Sync scope: only the 16 CTAs sharing a batch tile (group bt).
#define WPAD 260
#define SMEM_FLOATS (64 * WPAD + 32 * WPAD)

__global__ void lstm_persist_kernel(const float* __restrict__ xp,   // [T,B,4H]
                                    const float* __restrict__ Whh,  // [4H,H]
                                    float* __restrict__ hbuf,       // [2][B,H]
                                    float* __restrict__ hseq)       // [T,B,H]|null
{
    extern __shared__ float sm[];
    float* Ws = sm;               // [64][WPAD]
    float* Hs = sm + 64 * WPAD;   // [32][WPAD]

    const int tid = threadIdx.x;
    const int jt  = blockIdx.x & 15;
    const int bt  = blockIdx.x >> 4;
    const int jj  = jt * 16;
    const int bb  = bt * 32;
    const int jl  = tid >> 3;    // 0..15 hidden unit within tile
    const int br  = tid & 7;     // batch rows br, br+8, br+16, br+24
    const int j   = jj + jl;

    // ---- load W_hh slice once: smem row = g*16 + jloc
#pragma unroll
    for (int i = 0; i < 32; i++) {
        int lin  = i * 128 + tid;
        int srow = lin >> 6;
        int c4   = (lin & 63) * 4;
        int g    = srow >> 4;
        int jloc = srow & 15;
        *(float4*)&Ws[srow * WPAD + c4] =
            *(const float4*)(Whh + (size_t)(g * HH + jj + jloc) * HH + c4);
    }

    float cacc[4] = {0.f, 0.f, 0.f, 0.f};
    __syncthreads();

    for (int t = 0; t < TT; t++) {
        // ---- load h tile (32 x 256) from ping buffer, L2-coherent
        const float* hin = hbuf + (size_t)(t & 1) * BHH;
#pragma unroll
        for (int i = 0; i < 16; i++) {
            int lin = i * 128 + tid;
            int row = lin >> 6;
            int c4  = (lin & 63) * 4;
            float4 v = __ldcg((const float4*)(hin + (size_t)(bb + row) * HH + c4));
            *(float4*)&Hs[row * WPAD + c4] = v;
        }
        __syncthreads();

        // ---- prefetch x_proj values for this step
        float xv[4][4];
        {
            const float* xpt = xp + (size_t)t * BB * G4;
#pragma unroll
            for (int m = 0; m < 4; m++) {
                const float* xr = xpt + (size_t)(bb + br + 8 * m) * G4;
#pragma unroll
                for (int g = 0; g < 4; g++)
                    xv[m][g] = __ldg(xr + g * HH + j);
            }
        }

        // ---- GEMM (f32x2, k packed in pairs): acc[m][g] = h[b_m,:].Whh[g,j,:]
        ull acc2[4][4];
#pragma unroll
        for (int m = 0; m < 4; m++)
#pragma unroll
            for (int g = 0; g < 4; g++) acc2[m][g] = 0ull;

#pragma unroll 4
        for (int k = 0; k < HH; k += 4) {
            ulonglong2 h2[4], w2[4];
#pragma unroll
            for (int m = 0; m < 4; m++)
                h2[m] = *(ulonglong2*)&Hs[(br + 8 * m) * WPAD + k];
#pragma unroll
            for (int g = 0; g < 4; g++)
                w2[g] = *(ulonglong2*)&Ws[(g * 16 + jl) * WPAD + k];
#pragma unroll
            for (int m = 0; m < 4; m++)
#pragma unroll
                for (int g = 0; g < 4; g++) {
                    ffma2(acc2[m][g], h2[m].x, w2[g].x);
                    ffma2(acc2[m][g], h2[m].y, w2[g].y);
                }
        }

        // ---- gates + state update
        float* hout = hbuf + (size_t)((t + 1) & 1) * BHH;
#pragma unroll
        for (int m = 0; m < 4; m++) {
            int b = bb + br + 8 * m;
            float vi = red2(acc2[m][0]) + xv[m][0];
            float vf = red2(acc2[m][1]) + xv[m][1];
            float vg = red2(acc2[m][2]) + xv[m][2];
            float vo = red2(acc2[m][3]) + xv[m][3];

            float ig = fsig(vi);
            float fg = fsig(vf);
            float gg = ftanh(vg);
            float og = fsig(vo);

            float cn = fg * cacc[m] + ig * gg;
            cacc[m] = cn;
            float hn = og * ftanh(cn);
            __stcg(hout + (size_t)b * HH + j, hn);
            if (hseq != nullptr) hseq[(size_t)t * BHH + (size_t)b * HH + j] = hn;
        }

        // ---- group barrier: only the 16 CTAs sharing batch tile bt
        __syncthreads();
        if (tid == 0) {
            __threadfence();
            atomicAdd(&g_count[bt], 1u);
            unsigned target = (unsigned)(t + 1) * GROUP_CTAS;
            while (*((volatile unsigned*)&g_count[bt]) < target) {}
            __threadfence();
        }
        __syncthreads();
    }
}

// ---------------- launcher ---------------------------------------------------
extern "C" void kernel_launch(void* const* d_in, const int* in_sizes, int n_in,
                              void* d_out, int out_size)
{
    const float* x     = (const float*)d_in[0];
    const float* W_ih0 = (const float*)d_in[1];
    const float* W_hh0 = (const float*)d_in[2];
    const float* b_ih0 = (const float*)d_in[3];
    const float* b_hh0 = (const float*)d_in[4];
    const float* W_ih1 = (const float*)d_in[5];
    const float* W_hh1 = (const float*)d_in[6];
    const float* b_ih1 = (const float*)d_in[7];
    const float* b_hh1 = (const float*)d_in[8];
    const float* W_fc  = (const float*)d_in[9];
    float* outp = (float*)d_out;
    (void)in_sizes; (void)n_in; (void)out_size;

    float *XP, *HSEQ, *Hbuf;
    cudaGetSymbolAddress((void**)&XP,   g_XP);
    cudaGetSymbolAddress((void**)&HSEQ, g_HSEQ);
    cudaGetSymbolAddress((void**)&Hbuf, g_h);

    static bool attr_set = false;
    if (!attr_set) {
        cudaFuncSetAttribute(lstm_persist_kernel,
                             cudaFuncAttributeMaxDynamicSharedMemorySize,
                             SMEM_FLOATS * (int)sizeof(float));
        attr_set = true;
    }

    const dim3 gemmBlk(256);
    const size_t smemB = SMEM_FLOATS * sizeof(float);

    // ---------- layer 0 ----------
    init_kernel<<<(BHH + 255) / 256, 256>>>();
    gemm_bias_kernel<DIN><<<dim3(16, 4, TT), gemmBlk>>>(
        x, (size_t)TT * DIN, (size_t)DIN, W_ih0, b_ih0, b_hh0, XP, G4);
    lstm_persist_kernel<<<NB_CTAS, 128, smemB>>>(XP, W_hh0, Hbuf, HSEQ);

    // ---------- layer 1 ----------
    init_kernel<<<(BHH + 255) / 256, 256>>>();
    gemm_bias_kernel<HH><<<dim3(16, 4, TT), gemmBlk>>>(
        HSEQ, (size_t)HH, (size_t)BB * HH, W_ih1, b_ih1, b_hh1, XP, G4);
    lstm_persist_kernel<<<NB_CTAS, 128, smemB>>>(XP, W_hh1, Hbuf, nullptr);

    // ---------- final FC: out = h_last @ W_fc^T (layer-1 last h in buf 0) ----
    gemm_bias_kernel<HH><<<dim3(2, 4, 1), gemmBlk>>>(
        Hbuf, (size_t)HH, 0, W_fc, nullptr, nullptr, outp, OUTF);
}